// round 3
// baseline (speedup 1.0000x reference)
#include <cuda_runtime.h>
#include <cstddef>

#define NN 50000
#define EE 800000
#define MULC 32
#define CAP 64                        // bucket capacity per node (deg = 16 +/- 4)

#define INV8   0.3535533905932738f    // 1/sqrt(8)
#define INVH   0.3535533905932738f    // 1/sqrt(HID=8)
#define INV3   0.5773502691896258f    // 1/sqrt(3)
#define LIN1   0.1767766952966369f    // 1/sqrt(32)
#define LIN2   0.125f                 // 1/sqrt(64)
#define INVSC  0.08838834764831845f   // 1/sqrt(128)

// Scratch (device globals — no runtime allocation allowed)
__device__ __align__(16) float g_s1v[(size_t)NN * MULC * 4]; // (n,u,{s1,v1x,v1y,v1z})
__device__ __align__(16) float g_sc [(size_t)NN * 128];      // sc_s[32] | sc_v(u,i)
__device__ int g_cnt[NN];
__device__ int g_bke[(size_t)NN * CAP];                      // edge ids per node
__device__ int g_bkn[(size_t)NN * CAP];                      // neighbor ids per node

// ---------------------------------------------------------------------------
// dtype sniff: JAX default config demotes the requested int64 edge_index to
// int32. For int64 (LE, values < 2^31) the high words of the first 4 entries
// are all zero; for random int32 in [0,50000) that has P ~ 1.6e-19.
// ---------------------------------------------------------------------------
__device__ __forceinline__ int sniff_is64(const int* __restrict__ p) {
    return (__ldg(p + 1) == 0) & (__ldg(p + 3) == 0) &
           (__ldg(p + 5) == 0) & (__ldg(p + 7) == 0);
}

// ---------------------------------------------------------------------------
// Kernel 0: zero per-node counters (must run every graph replay)
// ---------------------------------------------------------------------------
__global__ void __launch_bounds__(256) k_zero() {
    int i = blockIdx.x * 256 + threadIdx.x;
    if (i < NN) g_cnt[i] = 0;
}

// ---------------------------------------------------------------------------
// Kernel 1: bucket edges by center node
// ---------------------------------------------------------------------------
__global__ void __launch_bounds__(256) k_place(const int* __restrict__ eidx32)
{
    int e = blockIdx.x * 256 + threadIdx.x;
    if (e >= EE) return;
    int ctr, nbr;
    if (sniff_is64(eidx32)) {
        const long long* p = (const long long*)eidx32;
        ctr = (int)p[e];
        nbr = (int)p[EE + e];
    } else {
        ctr = eidx32[e];
        nbr = eidx32[EE + e];
    }
    int slot = atomicAdd(&g_cnt[ctr], 1);
    if (slot < CAP) {
        g_bke[(size_t)ctr * CAP + slot] = e;
        g_bkn[(size_t)ctr * CAP + slot] = nbr;
    }
}

// ---------------------------------------------------------------------------
// Kernel 2: per-node pre-work (s1/v1 + skip connection). 2 nodes per warp.
// ---------------------------------------------------------------------------
__global__ void __launch_bounds__(256) k_pre(
    const float* __restrict__ nf, const float* __restrict__ nattr,
    const float* __restrict__ W1s, const float* __restrict__ W1v,
    const float* __restrict__ WscS, const float* __restrict__ WscV)
{
    __shared__ float sW1s[1024], sW1v[1024], sWscS[4096], sWscV[4096];
    int tid = threadIdx.x;
    for (int i = tid; i < 1024; i += 256) { sW1s[i] = W1s[i]; sW1v[i] = W1v[i]; }
    for (int i = tid; i < 4096; i += 256) { sWscS[i] = WscS[i]; sWscV[i] = WscV[i]; }
    __syncthreads();

    int warp = blockIdx.x * 8 + (tid >> 5);
    int lane = tid & 31;
    int n0 = warp * 2, n1 = warp * 2 + 1;
    if (n1 >= NN) return;

    int v = lane;
    const float* f0 = nf + (size_t)n0 * 128;
    const float* f1 = nf + (size_t)n1 * 128;
    float s0r = f0[v], s1r = f1[v];
    float v0x = f0[32 + v*3], v0y = f0[33 + v*3], v0z = f0[34 + v*3];
    float v1x = f1[32 + v*3], v1y = f1[33 + v*3], v1z = f1[34 + v*3];
    float4 a0 = ((const float4*)nattr)[n0];
    float4 a1 = ((const float4*)nattr)[n1];

    float s1a = 0.f, s1b = 0.f;
    float p0x = 0.f, p0y = 0.f, p0z = 0.f, p1x = 0.f, p1y = 0.f, p1z = 0.f;
    float scs0 = 0.f, scs1 = 0.f;
    float q0x = 0.f, q0y = 0.f, q0z = 0.f, q1x = 0.f, q1y = 0.f, q1z = 0.f;

    #pragma unroll
    for (int u = 0; u < 32; u++) {
        float su0 = __shfl_sync(0xffffffffu, s0r, u);
        float su1 = __shfl_sync(0xffffffffu, s1r, u);
        float ux0 = __shfl_sync(0xffffffffu, v0x, u);
        float uy0 = __shfl_sync(0xffffffffu, v0y, u);
        float uz0 = __shfl_sync(0xffffffffu, v0z, u);
        float ux1 = __shfl_sync(0xffffffffu, v1x, u);
        float uy1 = __shfl_sync(0xffffffffu, v1y, u);
        float uz1 = __shfl_sync(0xffffffffu, v1z, u);

        float w1s = sW1s[u*32 + v];
        float w1v = sW1v[u*32 + v];
        float c0 = sWscS[u*128 +      v], c1 = sWscS[u*128 + 32 + v];
        float c2 = sWscS[u*128 + 64 + v], c3 = sWscS[u*128 + 96 + v];
        float d0 = sWscV[u*128 +      v], d1 = sWscV[u*128 + 32 + v];
        float d2 = sWscV[u*128 + 64 + v], d3 = sWscV[u*128 + 96 + v];

        float gs0 = a0.x*c0 + a0.y*c1 + a0.z*c2 + a0.w*c3;
        float gs1 = a1.x*c0 + a1.y*c1 + a1.z*c2 + a1.w*c3;
        float gv0 = a0.x*d0 + a0.y*d1 + a0.z*d2 + a0.w*d3;
        float gv1 = a1.x*d0 + a1.y*d1 + a1.z*d2 + a1.w*d3;

        s1a += su0*w1s;  s1b += su1*w1s;
        p0x += ux0*w1v;  p0y += uy0*w1v;  p0z += uz0*w1v;
        p1x += ux1*w1v;  p1y += uy1*w1v;  p1z += uz1*w1v;
        scs0 += su0*gs0; scs1 += su1*gs1;
        q0x += ux0*gv0;  q0y += uy0*gv0;  q0z += uz0*gv0;
        q1x += ux1*gv1;  q1y += uy1*gv1;  q1z += uz1*gv1;
    }

    ((float4*)g_s1v)[(size_t)n0*32 + v] = make_float4(s1a*LIN1, p0x*LIN1, p0y*LIN1, p0z*LIN1);
    ((float4*)g_s1v)[(size_t)n1*32 + v] = make_float4(s1b*LIN1, p1x*LIN1, p1y*LIN1, p1z*LIN1);

    float* sc0 = g_sc + (size_t)n0 * 128;
    float* sc1 = g_sc + (size_t)n1 * 128;
    sc0[v] = scs0 * INVSC;
    sc0[32 + v*3 + 0] = q0x * INVSC;
    sc0[32 + v*3 + 1] = q0y * INVSC;
    sc0[32 + v*3 + 2] = q0z * INVSC;
    sc1[v] = scs1 * INVSC;
    sc1[32 + v*3 + 0] = q1x * INVSC;
    sc1[32 + v*3 + 1] = q1y * INVSC;
    sc1[32 + v*3 + 2] = q1z * INVSC;
}

// ---------------------------------------------------------------------------
// Kernel 3: per-node edge gather + accumulate + W2 + skip (fused epilogue).
// One warp per node, lane = channel u (accum) / output channel v (epilogue).
// No floating-point atomics anywhere.
// ---------------------------------------------------------------------------
__global__ void __launch_bounds__(256) k_gather(
    const float* __restrict__ ee, const float* __restrict__ eattr,
    const float* __restrict__ Wfc1, const float* __restrict__ Wfc2,
    const float* __restrict__ W2s, const float* __restrict__ W2v,
    float* __restrict__ out)
{
    __shared__ float sF1[64];
    __shared__ float sWs[2048], sWv[2048];
    __shared__ float stage[8 * 256];
    int tid = threadIdx.x;
    int lane = tid & 31;
    for (int i = tid; i < 64;   i += 256) sF1[i] = Wfc1[i];
    for (int i = tid; i < 2048; i += 256) { sWs[i] = W2s[i]; sWv[i] = W2v[i]; }
    __syncthreads();

    // Hoisted radial-MLP weights (registers, not smem — kills per-edge LDS)
    int j = lane & 7;
    float f1r[8];
    #pragma unroll
    for (int b = 0; b < 8; b++) f1r[b] = sF1[b*8 + j];
    float f2a[8], f2b[8], f2c[8], f2d[8];
    #pragma unroll
    for (int k = 0; k < 8; k++) {
        f2a[k] = __ldg(Wfc2 + k*128 +      lane);
        f2b[k] = __ldg(Wfc2 + k*128 + 32 + lane);
        f2c[k] = __ldg(Wfc2 + k*128 + 64 + lane);
        f2d[k] = __ldg(Wfc2 + k*128 + 96 + lane);
    }

    int n = blockIdx.x * 8 + (tid >> 5);
    if (n >= NN) return;

    int deg = g_cnt[n];
    if (deg > CAP) deg = CAP;

    // prefetch bucket rows (lane-parallel)
    const int* be = g_bke + (size_t)n * CAP;
    const int* bn = g_bkn + (size_t)n * CAP;
    int e0 = be[lane], e1 = be[32 + lane];
    int m0 = bn[lane], m1 = bn[32 + lane];

    float a0 = 0.f, a1 = 0.f, a2 = 0.f, a3 = 0.f;   // s0, v1xyz
    float a4 = 0.f, a5 = 0.f, a6 = 0.f, a7 = 0.f;   // s3, v2xyz

    for (int i = 0; i < deg; i++) {
        int eid = __shfl_sync(0xffffffffu, (i < 32) ? e0 : e1, i & 31);
        int nbr = __shfl_sync(0xffffffffu, (i < 32) ? m0 : m1, i & 31);

        float4 ea = __ldg((const float4*)eattr + eid);            // es, ev0..2
        float4 eA = __ldg((const float4*)ee + (size_t)eid*2);
        float4 eB = __ldg((const float4*)ee + (size_t)eid*2 + 1);
        float4 xg = __ldg((const float4*)g_s1v + (size_t)nbr*32 + lane);

        // radial MLP hidden (lane computes h[lane&7], 4x redundant)
        float x = eA.x*f1r[0] + eA.y*f1r[1] + eA.z*f1r[2] + eA.w*f1r[3]
                + eB.x*f1r[4] + eB.y*f1r[5] + eB.z*f1r[6] + eB.w*f1r[7];
        x *= INV8;
        float hj = x / (1.f + __expf(-x));                        // silu

        float w0 = 0.f, w1 = 0.f, w2 = 0.f, w3 = 0.f;
        #pragma unroll
        for (int k = 0; k < 8; k++) {
            float hk = __shfl_sync(0xffffffffu, hj, k);
            w0 += hk * f2a[k];
            w1 += hk * f2b[k];
            w2 += hk * f2c[k];
            w3 += hk * f2d[k];
        }
        w0 *= INVH; w1 *= INVH; w2 *= INVH; w3 *= INVH;

        float dot = xg.y*ea.y + xg.z*ea.z + xg.w*ea.w;
        float av = w1 * xg.x;         // v1 = av * ev
        float bv = w2 * ea.x;         // v2 = bv * xv
        a0 += w0 * xg.x * ea.x;
        a1 += av * ea.y;  a2 += av * ea.z;  a3 += av * ea.w;
        a4 += w3 * dot * INV3;
        a5 += bv * xg.y;  a6 += bv * xg.z;  a7 += bv * xg.w;
    }

    // Fused epilogue: stage accumulators, W2 matvec, skip add, write out
    float* st = stage + (tid >> 5) * 256;
    ((float4*)st)[lane*2]     = make_float4(a0, a1, a2, a3);
    ((float4*)st)[lane*2 + 1] = make_float4(a4, a5, a6, a7);
    __syncwarp();

    float os = 0.f, ox = 0.f, oy = 0.f, oz = 0.f;
    #pragma unroll
    for (int u = 0; u < 32; u++) {
        float4 B0 = ((const float4*)st)[u*2];        // broadcast reads
        float4 B1 = ((const float4*)st)[u*2 + 1];
        float ws0 = sWs[u*32 + lane], ws1 = sWs[(u + 32)*32 + lane];
        float wv0 = sWv[u*32 + lane], wv1 = sWv[(u + 32)*32 + lane];
        os += B0.x*ws0 + B1.x*ws1;
        ox += B0.y*wv0 + B1.y*wv1;
        oy += B0.z*wv0 + B1.z*wv1;
        oz += B0.w*wv0 + B1.w*wv1;
    }

    const float* sc = g_sc + (size_t)n * 128;
    float* o = out + (size_t)n * 128;
    o[lane]            = os*LIN2 + sc[lane];
    o[32 + lane*3 + 0] = ox*LIN2 + sc[32 + lane*3 + 0];
    o[32 + lane*3 + 1] = oy*LIN2 + sc[32 + lane*3 + 1];
    o[32 + lane*3 + 2] = oz*LIN2 + sc[32 + lane*3 + 2];
}

// ---------------------------------------------------------------------------
extern "C" void kernel_launch(void* const* d_in, const int* in_sizes, int n_in,
                              void* d_out, int out_size)
{
    const float* ee    = (const float*)d_in[0];
    const float* nattr = (const float*)d_in[1];
    const float* nf    = (const float*)d_in[2];
    const int*   eidx  = (const int*)d_in[3];    // int32 or int64 — sniffed in-kernel
    const float* eattr = (const float*)d_in[4];
    const float* W1s   = (const float*)d_in[5];
    const float* W1v   = (const float*)d_in[6];
    const float* Wfc1  = (const float*)d_in[7];
    const float* Wfc2  = (const float*)d_in[8];
    const float* W2s   = (const float*)d_in[9];
    const float* W2v   = (const float*)d_in[10];
    const float* WscS  = (const float*)d_in[11];
    const float* WscV  = (const float*)d_in[12];

    k_zero  <<<196,  256>>>();
    k_place <<<3125, 256>>>(eidx);
    k_pre   <<<3125, 256>>>(nf, nattr, W1s, W1v, WscS, WscV);
    k_gather<<<6250, 256>>>(ee, eattr, Wfc1, Wfc2, W2s, W2v, (float*)d_out);
}

// round 4
// speedup vs baseline: 2.0423x; 2.0423x over previous
#include <cuda_runtime.h>
#include <cstddef>

#define NN 50000
#define EE 800000
#define MULC 32
#define CAP 64                        // bucket capacity per node (deg = 16 +/- 4)

#define INV8   0.3535533905932738f    // 1/sqrt(8)
#define INVH   0.3535533905932738f    // 1/sqrt(HID=8)
#define INV3   0.5773502691896258f    // 1/sqrt(3)
#define LIN1   0.1767766952966369f    // 1/sqrt(32)
#define LIN2   0.125f                 // 1/sqrt(64)
#define INVSC  0.08838834764831845f   // 1/sqrt(128)

// Scratch (device globals — no runtime allocation allowed)
__device__ __align__(16) float g_s1v[(size_t)NN * MULC * 4]; // (n,u,{s1,v1x,v1y,v1z})
__device__ __align__(16) float g_sc [(size_t)NN * 128];      // sc_s[32] | sc_v(u,i)
__device__ __align__(16) float g_h  [(size_t)EE * 8];        // per-edge silu(MLP)*INVH
__device__ int g_cnt[NN];
__device__ int g_bke[(size_t)NN * CAP];                      // edge ids per node
__device__ int g_bkn[(size_t)NN * CAP];                      // neighbor ids per node

// ---------------------------------------------------------------------------
// dtype sniff: JAX default config demotes the requested int64 edge_index to
// int32. For int64 (LE, values < 2^31) the high words of the first 4 entries
// are all zero; for random int32 in [0,50000) that has P ~ 1.6e-19.
// ---------------------------------------------------------------------------
__device__ __forceinline__ int sniff_is64(const int* __restrict__ p) {
    return (__ldg(p + 1) == 0) & (__ldg(p + 3) == 0) &
           (__ldg(p + 5) == 0) & (__ldg(p + 7) == 0);
}

// ---------------------------------------------------------------------------
// Kernel 0: zero per-node counters (must run every graph replay)
// ---------------------------------------------------------------------------
__global__ void __launch_bounds__(256) k_zero() {
    int i = blockIdx.x * 256 + threadIdx.x;
    if (i < NN) g_cnt[i] = 0;
}

// ---------------------------------------------------------------------------
// Kernel 1: bucket edges by center node AND precompute radial-MLP hidden h[8]
// (thread per edge, fully parallel — removes silu + shfl from the gather loop)
// ---------------------------------------------------------------------------
__global__ void __launch_bounds__(256) k_place(
    const int* __restrict__ eidx32, const float* __restrict__ ee,
    const float* __restrict__ Wfc1)
{
    __shared__ float sF1[64];
    int tid = threadIdx.x;
    if (tid < 64) sF1[tid] = Wfc1[tid];
    __syncthreads();

    int e = blockIdx.x * 256 + tid;
    if (e >= EE) return;

    int ctr, nbr;
    if (sniff_is64(eidx32)) {
        const long long* p = (const long long*)eidx32;
        ctr = (int)p[e];
        nbr = (int)p[EE + e];
    } else {
        ctr = eidx32[e];
        nbr = eidx32[EE + e];
    }
    int slot = atomicAdd(&g_cnt[ctr], 1);
    if (slot < CAP) {
        g_bke[(size_t)ctr * CAP + slot] = e;
        g_bkn[(size_t)ctr * CAP + slot] = nbr;
    }

    float4 A = __ldg((const float4*)ee + (size_t)e*2);
    float4 B = __ldg((const float4*)ee + (size_t)e*2 + 1);
    float h[8];
    #pragma unroll
    for (int j = 0; j < 8; j++) {
        float x = A.x*sF1[j]      + A.y*sF1[8 + j]  + A.z*sF1[16 + j] + A.w*sF1[24 + j]
                + B.x*sF1[32 + j] + B.y*sF1[40 + j] + B.z*sF1[48 + j] + B.w*sF1[56 + j];
        x *= INV8;
        h[j] = INVH * x / (1.f + __expf(-x));       // silu, INVH folded in
    }
    ((float4*)g_h)[(size_t)e*2]     = make_float4(h[0], h[1], h[2], h[3]);
    ((float4*)g_h)[(size_t)e*2 + 1] = make_float4(h[4], h[5], h[6], h[7]);
}

// ---------------------------------------------------------------------------
// Kernel 2: per-node pre-work (s1/v1 + skip connection). 2 nodes per warp.
// SHFL broadcasts replaced by smem stage + LDS broadcast (MIO relief).
// ---------------------------------------------------------------------------
__global__ void __launch_bounds__(256) k_pre(
    const float* __restrict__ nf, const float* __restrict__ nattr,
    const float* __restrict__ W1s, const float* __restrict__ W1v,
    const float* __restrict__ WscS, const float* __restrict__ WscV)
{
    __shared__ float sW1s[1024], sW1v[1024], sWscS[4096], sWscV[4096];
    __shared__ float sStage[8 * 256];
    int tid = threadIdx.x;
    for (int i = tid; i < 1024; i += 256) { sW1s[i] = W1s[i]; sW1v[i] = W1v[i]; }
    for (int i = tid; i < 4096; i += 256) { sWscS[i] = WscS[i]; sWscV[i] = WscV[i]; }
    __syncthreads();

    int warp = blockIdx.x * 8 + (tid >> 5);
    int lane = tid & 31;
    int n0 = warp * 2, n1 = warp * 2 + 1;
    if (n1 >= NN) return;

    int v = lane;
    const float* f0 = nf + (size_t)n0 * 128;
    const float* f1 = nf + (size_t)n1 * 128;
    float4 a0 = ((const float4*)nattr)[n0];
    float4 a1 = ((const float4*)nattr)[n1];

    float* stg = sStage + (tid >> 5) * 256;
    stg[       lane] = f0[v];
    stg[ 32 +  lane] = f0[32 + v*3];
    stg[ 64 +  lane] = f0[33 + v*3];
    stg[ 96 +  lane] = f0[34 + v*3];
    stg[128 +  lane] = f1[v];
    stg[160 +  lane] = f1[32 + v*3];
    stg[192 +  lane] = f1[33 + v*3];
    stg[224 +  lane] = f1[34 + v*3];
    __syncwarp();

    float s1a = 0.f, s1b = 0.f;
    float p0x = 0.f, p0y = 0.f, p0z = 0.f, p1x = 0.f, p1y = 0.f, p1z = 0.f;
    float scs0 = 0.f, scs1 = 0.f;
    float q0x = 0.f, q0y = 0.f, q0z = 0.f, q1x = 0.f, q1y = 0.f, q1z = 0.f;

    #pragma unroll
    for (int u = 0; u < 32; u++) {
        float su0 = stg[u],        ux0 = stg[32 + u];
        float uy0 = stg[64 + u],   uz0 = stg[96 + u];
        float su1 = stg[128 + u],  ux1 = stg[160 + u];
        float uy1 = stg[192 + u],  uz1 = stg[224 + u];

        float w1s = sW1s[u*32 + v];
        float w1v = sW1v[u*32 + v];
        float c0 = sWscS[u*128 +      v], c1 = sWscS[u*128 + 32 + v];
        float c2 = sWscS[u*128 + 64 + v], c3 = sWscS[u*128 + 96 + v];
        float d0 = sWscV[u*128 +      v], d1 = sWscV[u*128 + 32 + v];
        float d2 = sWscV[u*128 + 64 + v], d3 = sWscV[u*128 + 96 + v];

        float gs0 = a0.x*c0 + a0.y*c1 + a0.z*c2 + a0.w*c3;
        float gs1 = a1.x*c0 + a1.y*c1 + a1.z*c2 + a1.w*c3;
        float gv0 = a0.x*d0 + a0.y*d1 + a0.z*d2 + a0.w*d3;
        float gv1 = a1.x*d0 + a1.y*d1 + a1.z*d2 + a1.w*d3;

        s1a += su0*w1s;  s1b += su1*w1s;
        p0x += ux0*w1v;  p0y += uy0*w1v;  p0z += uz0*w1v;
        p1x += ux1*w1v;  p1y += uy1*w1v;  p1z += uz1*w1v;
        scs0 += su0*gs0; scs1 += su1*gs1;
        q0x += ux0*gv0;  q0y += uy0*gv0;  q0z += uz0*gv0;
        q1x += ux1*gv1;  q1y += uy1*gv1;  q1z += uz1*gv1;
    }

    ((float4*)g_s1v)[(size_t)n0*32 + v] = make_float4(s1a*LIN1, p0x*LIN1, p0y*LIN1, p0z*LIN1);
    ((float4*)g_s1v)[(size_t)n1*32 + v] = make_float4(s1b*LIN1, p1x*LIN1, p1y*LIN1, p1z*LIN1);

    float* sc0 = g_sc + (size_t)n0 * 128;
    float* sc1 = g_sc + (size_t)n1 * 128;
    sc0[v] = scs0 * INVSC;
    sc0[32 + v*3 + 0] = q0x * INVSC;
    sc0[32 + v*3 + 1] = q0y * INVSC;
    sc0[32 + v*3 + 2] = q0z * INVSC;
    sc1[v] = scs1 * INVSC;
    sc1[32 + v*3 + 0] = q1x * INVSC;
    sc1[32 + v*3 + 1] = q1y * INVSC;
    sc1[32 + v*3 + 2] = q1z * INVSC;
}

// ---------------------------------------------------------------------------
// Kernel 3: per-node edge gather + accumulate + W2 + skip (fused epilogue).
// One warp per node; no shfl, no FP atomics; ILP-2 unrolled; 2 blocks/SM.
// ---------------------------------------------------------------------------
__global__ void __launch_bounds__(256, 2) k_gather(
    const float* __restrict__ eattr, const float* __restrict__ Wfc2,
    const float* __restrict__ W2s, const float* __restrict__ W2v,
    float* __restrict__ out)
{
    __shared__ float sWs[2048], sWv[2048];
    __shared__ float stage[8 * 256];
    __shared__ int   sBe[8 * CAP], sBn[8 * CAP];
    int tid = threadIdx.x;
    int lane = tid & 31;
    int w = tid >> 5;
    for (int i = tid; i < 2048; i += 256) { sWs[i] = W2s[i]; sWv[i] = W2v[i]; }

    // Wfc2 columns in registers (broadcast-uniform per lane)
    float f2a[8], f2b[8], f2c[8], f2d[8];
    #pragma unroll
    for (int k = 0; k < 8; k++) {
        f2a[k] = __ldg(Wfc2 + k*128 +      lane);
        f2b[k] = __ldg(Wfc2 + k*128 + 32 + lane);
        f2c[k] = __ldg(Wfc2 + k*128 + 64 + lane);
        f2d[k] = __ldg(Wfc2 + k*128 + 96 + lane);
    }
    __syncthreads();

    int n = blockIdx.x * 8 + w;
    if (n >= NN) return;

    int deg = g_cnt[n];
    if (deg > CAP) deg = CAP;

    // stage bucket in smem (inner loop uses LDS broadcast, not SHFL)
    const int* be = g_bke + (size_t)n * CAP;
    const int* bn = g_bkn + (size_t)n * CAP;
    sBe[w*CAP + lane]      = be[lane];
    sBe[w*CAP + 32 + lane] = be[32 + lane];
    sBn[w*CAP + lane]      = bn[lane];
    sBn[w*CAP + 32 + lane] = bn[32 + lane];
    __syncwarp();

    float a0 = 0.f, a1 = 0.f, a2 = 0.f, a3 = 0.f;   // s0, v1xyz
    float a4 = 0.f, a5 = 0.f, a6 = 0.f, a7 = 0.f;   // s3, v2xyz

    #define EDGE_BODY(IDX)                                                     \
    {                                                                          \
        int eid = sBe[w*CAP + (IDX)];                                          \
        int nbr = sBn[w*CAP + (IDX)];                                          \
        float4 ea = __ldg((const float4*)eattr + eid);                         \
        float4 h0 = __ldg((const float4*)g_h + (size_t)eid*2);                 \
        float4 h1 = __ldg((const float4*)g_h + (size_t)eid*2 + 1);             \
        float4 xg = __ldg((const float4*)g_s1v + (size_t)nbr*32 + lane);       \
        float w0 = h0.x*f2a[0] + h0.y*f2a[1] + h0.z*f2a[2] + h0.w*f2a[3]       \
                 + h1.x*f2a[4] + h1.y*f2a[5] + h1.z*f2a[6] + h1.w*f2a[7];      \
        float w1 = h0.x*f2b[0] + h0.y*f2b[1] + h0.z*f2b[2] + h0.w*f2b[3]       \
                 + h1.x*f2b[4] + h1.y*f2b[5] + h1.z*f2b[6] + h1.w*f2b[7];      \
        float w2 = h0.x*f2c[0] + h0.y*f2c[1] + h0.z*f2c[2] + h0.w*f2c[3]       \
                 + h1.x*f2c[4] + h1.y*f2c[5] + h1.z*f2c[6] + h1.w*f2c[7];      \
        float w3 = h0.x*f2d[0] + h0.y*f2d[1] + h0.z*f2d[2] + h0.w*f2d[3]       \
                 + h1.x*f2d[4] + h1.y*f2d[5] + h1.z*f2d[6] + h1.w*f2d[7];      \
        float dot = xg.y*ea.y + xg.z*ea.z + xg.w*ea.w;                         \
        float av = w1 * xg.x;                                                  \
        float bv = w2 * ea.x;                                                  \
        a0 += w0 * xg.x * ea.x;                                                \
        a1 += av * ea.y;  a2 += av * ea.z;  a3 += av * ea.w;                   \
        a4 += w3 * dot * INV3;                                                 \
        a5 += bv * xg.y;  a6 += bv * xg.z;  a7 += bv * xg.w;                   \
    }

    int i = 0;
    for (; i + 1 < deg; i += 2) {      // ILP-2: two edges' loads in flight
        EDGE_BODY(i);
        EDGE_BODY(i + 1);
    }
    if (i < deg) EDGE_BODY(i);
    #undef EDGE_BODY

    // Fused epilogue: stage accumulators, W2 matvec, skip add, write out
    float* st = stage + w * 256;
    ((float4*)st)[lane*2]     = make_float4(a0, a1, a2, a3);
    ((float4*)st)[lane*2 + 1] = make_float4(a4, a5, a6, a7);
    __syncwarp();

    float os = 0.f, ox = 0.f, oy = 0.f, oz = 0.f;
    #pragma unroll
    for (int u = 0; u < 32; u++) {
        float4 B0 = ((const float4*)st)[u*2];        // LDS broadcast
        float4 B1 = ((const float4*)st)[u*2 + 1];
        float ws0 = sWs[u*32 + lane], ws1 = sWs[(u + 32)*32 + lane];
        float wv0 = sWv[u*32 + lane], wv1 = sWv[(u + 32)*32 + lane];
        os += B0.x*ws0 + B1.x*ws1;
        ox += B0.y*wv0 + B1.y*wv1;
        oy += B0.z*wv0 + B1.z*wv1;
        oz += B0.w*wv0 + B1.w*wv1;
    }

    const float* sc = g_sc + (size_t)n * 128;
    float* o = out + (size_t)n * 128;
    o[lane]            = os*LIN2 + sc[lane];
    o[32 + lane*3 + 0] = ox*LIN2 + sc[32 + lane*3 + 0];
    o[32 + lane*3 + 1] = oy*LIN2 + sc[32 + lane*3 + 1];
    o[32 + lane*3 + 2] = oz*LIN2 + sc[32 + lane*3 + 2];
}

// ---------------------------------------------------------------------------
extern "C" void kernel_launch(void* const* d_in, const int* in_sizes, int n_in,
                              void* d_out, int out_size)
{
    const float* ee    = (const float*)d_in[0];
    const float* nattr = (const float*)d_in[1];
    const float* nf    = (const float*)d_in[2];
    const int*   eidx  = (const int*)d_in[3];    // int32 or int64 — sniffed in-kernel
    const float* eattr = (const float*)d_in[4];
    const float* W1s   = (const float*)d_in[5];
    const float* W1v   = (const float*)d_in[6];
    const float* Wfc1  = (const float*)d_in[7];
    const float* Wfc2  = (const float*)d_in[8];
    const float* W2s   = (const float*)d_in[9];
    const float* W2v   = (const float*)d_in[10];
    const float* WscS  = (const float*)d_in[11];
    const float* WscV  = (const float*)d_in[12];

    k_zero  <<<196,  256>>>();
    k_place <<<3125, 256>>>(eidx, ee, Wfc1);
    k_pre   <<<3125, 256>>>(nf, nattr, W1s, W1v, WscS, WscV);
    k_gather<<<6250, 256>>>(eattr, Wfc2, W2s, W2v, (float*)d_out);
}

// round 5
// speedup vs baseline: 2.7318x; 1.3376x over previous
#include <cuda_runtime.h>
#include <cstddef>

#define NN 50000
#define EE 800000
#define MULC 32
#define CAP 64                        // bucket capacity per node (deg = 16 +/- 4)

#define INV8   0.3535533905932738f    // 1/sqrt(8)
#define INVH   0.3535533905932738f    // 1/sqrt(HID=8)
#define INV3   0.5773502691896258f    // 1/sqrt(3)
#define LIN1   0.1767766952966369f    // 1/sqrt(32)
#define LIN2   0.125f                 // 1/sqrt(64)
#define INVSC  0.08838834764831845f   // 1/sqrt(128)

// Scratch (device globals — no runtime allocation allowed)
__device__ __align__(16) float g_s1v[(size_t)NN * MULC * 4]; // (n,u,{s1,v1x,v1y,v1z})
__device__ __align__(16) float g_sc [(size_t)NN * 128];      // sc_s[32] | sc_v(u,i)
__device__ __align__(16) float g_h  [(size_t)EE * 8];        // per-edge silu(MLP)*INVH
__device__ int g_cnt[NN];
__device__ int g_bke[(size_t)NN * CAP];                      // edge ids per node
__device__ int g_bkn[(size_t)NN * CAP];                      // neighbor ids per node

// ---------------------------------------------------------------------------
// dtype sniff: JAX default config demotes the requested int64 edge_index to
// int32. For int64 (LE, values < 2^31) the high words of the first 4 entries
// are all zero; for random int32 in [0,50000) that has P ~ 1.6e-19.
// ---------------------------------------------------------------------------
__device__ __forceinline__ int sniff_is64(const int* __restrict__ p) {
    return (__ldg(p + 1) == 0) & (__ldg(p + 3) == 0) &
           (__ldg(p + 5) == 0) & (__ldg(p + 7) == 0);
}

// ---------------------------------------------------------------------------
// Kernel 0: zero per-node counters (must run every graph replay)
// ---------------------------------------------------------------------------
__global__ void __launch_bounds__(256) k_zero() {
    int i = blockIdx.x * 256 + threadIdx.x;
    if (i < NN) g_cnt[i] = 0;
}

// ---------------------------------------------------------------------------
// Kernel 1: bucket edges by center node AND precompute radial-MLP hidden h[8]
// ---------------------------------------------------------------------------
__global__ void __launch_bounds__(256) k_place(
    const int* __restrict__ eidx32, const float* __restrict__ ee,
    const float* __restrict__ Wfc1)
{
    __shared__ float sF1[64];
    int tid = threadIdx.x;
    if (tid < 64) sF1[tid] = Wfc1[tid];
    __syncthreads();

    int e = blockIdx.x * 256 + tid;
    if (e >= EE) return;

    int ctr, nbr;
    if (sniff_is64(eidx32)) {
        const long long* p = (const long long*)eidx32;
        ctr = (int)p[e];
        nbr = (int)p[EE + e];
    } else {
        ctr = eidx32[e];
        nbr = eidx32[EE + e];
    }
    int slot = atomicAdd(&g_cnt[ctr], 1);
    if (slot < CAP) {
        g_bke[(size_t)ctr * CAP + slot] = e;
        g_bkn[(size_t)ctr * CAP + slot] = nbr;
    }

    float4 A = __ldg((const float4*)ee + (size_t)e*2);
    float4 B = __ldg((const float4*)ee + (size_t)e*2 + 1);
    float h[8];
    #pragma unroll
    for (int j = 0; j < 8; j++) {
        float x = A.x*sF1[j]      + A.y*sF1[8 + j]  + A.z*sF1[16 + j] + A.w*sF1[24 + j]
                + B.x*sF1[32 + j] + B.y*sF1[40 + j] + B.z*sF1[48 + j] + B.w*sF1[56 + j];
        x *= INV8;
        h[j] = INVH * x / (1.f + __expf(-x));       // silu, INVH folded in
    }
    ((float4*)g_h)[(size_t)e*2]     = make_float4(h[0], h[1], h[2], h[3]);
    ((float4*)g_h)[(size_t)e*2 + 1] = make_float4(h[4], h[5], h[6], h[7]);
}

// ---------------------------------------------------------------------------
// Kernel 2: per-node pre-work (s1/v1 + skip connection). 2 nodes per warp.
// ---------------------------------------------------------------------------
__global__ void __launch_bounds__(256) k_pre(
    const float* __restrict__ nf, const float* __restrict__ nattr,
    const float* __restrict__ W1s, const float* __restrict__ W1v,
    const float* __restrict__ WscS, const float* __restrict__ WscV)
{
    __shared__ float sW1s[1024], sW1v[1024], sWscS[4096], sWscV[4096];
    __shared__ float sStage[8 * 256];
    int tid = threadIdx.x;
    for (int i = tid; i < 1024; i += 256) { sW1s[i] = W1s[i]; sW1v[i] = W1v[i]; }
    for (int i = tid; i < 4096; i += 256) { sWscS[i] = WscS[i]; sWscV[i] = WscV[i]; }
    __syncthreads();

    int warp = blockIdx.x * 8 + (tid >> 5);
    int lane = tid & 31;
    int n0 = warp * 2, n1 = warp * 2 + 1;
    if (n1 >= NN) return;

    int v = lane;
    const float* f0 = nf + (size_t)n0 * 128;
    const float* f1 = nf + (size_t)n1 * 128;
    float4 a0 = ((const float4*)nattr)[n0];
    float4 a1 = ((const float4*)nattr)[n1];

    float* stg = sStage + (tid >> 5) * 256;
    stg[       lane] = f0[v];
    stg[ 32 +  lane] = f0[32 + v*3];
    stg[ 64 +  lane] = f0[33 + v*3];
    stg[ 96 +  lane] = f0[34 + v*3];
    stg[128 +  lane] = f1[v];
    stg[160 +  lane] = f1[32 + v*3];
    stg[192 +  lane] = f1[33 + v*3];
    stg[224 +  lane] = f1[34 + v*3];
    __syncwarp();

    float s1a = 0.f, s1b = 0.f;
    float p0x = 0.f, p0y = 0.f, p0z = 0.f, p1x = 0.f, p1y = 0.f, p1z = 0.f;
    float scs0 = 0.f, scs1 = 0.f;
    float q0x = 0.f, q0y = 0.f, q0z = 0.f, q1x = 0.f, q1y = 0.f, q1z = 0.f;

    #pragma unroll
    for (int u = 0; u < 32; u++) {
        float su0 = stg[u],        ux0 = stg[32 + u];
        float uy0 = stg[64 + u],   uz0 = stg[96 + u];
        float su1 = stg[128 + u],  ux1 = stg[160 + u];
        float uy1 = stg[192 + u],  uz1 = stg[224 + u];

        float w1s = sW1s[u*32 + v];
        float w1v = sW1v[u*32 + v];
        float c0 = sWscS[u*128 +      v], c1 = sWscS[u*128 + 32 + v];
        float c2 = sWscS[u*128 + 64 + v], c3 = sWscS[u*128 + 96 + v];
        float d0 = sWscV[u*128 +      v], d1 = sWscV[u*128 + 32 + v];
        float d2 = sWscV[u*128 + 64 + v], d3 = sWscV[u*128 + 96 + v];

        float gs0 = a0.x*c0 + a0.y*c1 + a0.z*c2 + a0.w*c3;
        float gs1 = a1.x*c0 + a1.y*c1 + a1.z*c2 + a1.w*c3;
        float gv0 = a0.x*d0 + a0.y*d1 + a0.z*d2 + a0.w*d3;
        float gv1 = a1.x*d0 + a1.y*d1 + a1.z*d2 + a1.w*d3;

        s1a += su0*w1s;  s1b += su1*w1s;
        p0x += ux0*w1v;  p0y += uy0*w1v;  p0z += uz0*w1v;
        p1x += ux1*w1v;  p1y += uy1*w1v;  p1z += uz1*w1v;
        scs0 += su0*gs0; scs1 += su1*gs1;
        q0x += ux0*gv0;  q0y += uy0*gv0;  q0z += uz0*gv0;
        q1x += ux1*gv1;  q1y += uy1*gv1;  q1z += uz1*gv1;
    }

    ((float4*)g_s1v)[(size_t)n0*32 + v] = make_float4(s1a*LIN1, p0x*LIN1, p0y*LIN1, p0z*LIN1);
    ((float4*)g_s1v)[(size_t)n1*32 + v] = make_float4(s1b*LIN1, p1x*LIN1, p1y*LIN1, p1z*LIN1);

    float* sc0 = g_sc + (size_t)n0 * 128;
    float* sc1 = g_sc + (size_t)n1 * 128;
    sc0[v] = scs0 * INVSC;
    sc0[32 + v*3 + 0] = q0x * INVSC;
    sc0[32 + v*3 + 1] = q0y * INVSC;
    sc0[32 + v*3 + 2] = q0z * INVSC;
    sc1[v] = scs1 * INVSC;
    sc1[32 + v*3 + 0] = q1x * INVSC;
    sc1[32 + v*3 + 1] = q1y * INVSC;
    sc1[32 + v*3 + 2] = q1z * INVSC;
}

// ---------------------------------------------------------------------------
// Kernel 3: per-node gather. Chunked cooperative prefetch of uniform edge
// data into smem (batched MLP), ILP-4 scattered xg loads, fused W2 epilogue.
// 3 blocks/SM target.
// ---------------------------------------------------------------------------
__global__ void __launch_bounds__(256, 3) k_gather(
    const float* __restrict__ eattr, const float* __restrict__ Wfc2,
    const float* __restrict__ W2s, const float* __restrict__ W2v,
    float* __restrict__ out)
{
    __shared__ float sWs[2048], sWv[2048];
    __shared__ float4 pf[8][96];     // per-warp: [0:32)=ea [32:64)=h0 [64:96)=h1; reused as epilogue stage
    __shared__ int sBe[8][CAP], sBn[8][CAP];

    int tid = threadIdx.x;
    int lane = tid & 31;
    int w = tid >> 5;
    for (int i = tid; i < 2048; i += 256) { sWs[i] = W2s[i]; sWv[i] = W2v[i]; }

    // Wfc2 columns in registers
    float f2a[8], f2b[8], f2c[8], f2d[8];
    #pragma unroll
    for (int k = 0; k < 8; k++) {
        f2a[k] = __ldg(Wfc2 + k*128 +      lane);
        f2b[k] = __ldg(Wfc2 + k*128 + 32 + lane);
        f2c[k] = __ldg(Wfc2 + k*128 + 64 + lane);
        f2d[k] = __ldg(Wfc2 + k*128 + 96 + lane);
    }
    __syncthreads();

    int n = blockIdx.x * 8 + w;
    if (n >= NN) return;

    int deg = g_cnt[n];
    if (deg > CAP) deg = CAP;

    const int* be = g_bke + (size_t)n * CAP;
    const int* bn = g_bkn + (size_t)n * CAP;
    sBe[w][lane]      = be[lane];
    sBe[w][32 + lane] = be[32 + lane];
    sBn[w][lane]      = bn[lane];
    sBn[w][32 + lane] = bn[32 + lane];
    __syncwarp();

    float a0 = 0.f, a1 = 0.f, a2 = 0.f, a3 = 0.f;   // s0, v1xyz
    float a4 = 0.f, a5 = 0.f, a6 = 0.f, a7 = 0.f;   // s3, v2xyz

    #define COMPUTE(I, XG)                                                     \
    {                                                                          \
        float4 ea = pf[w][(I)];                                                \
        float4 h0 = pf[w][32 + (I)];                                           \
        float4 h1 = pf[w][64 + (I)];                                           \
        float w0 = h0.x*f2a[0] + h0.y*f2a[1] + h0.z*f2a[2] + h0.w*f2a[3]       \
                 + h1.x*f2a[4] + h1.y*f2a[5] + h1.z*f2a[6] + h1.w*f2a[7];      \
        float w1 = h0.x*f2b[0] + h0.y*f2b[1] + h0.z*f2b[2] + h0.w*f2b[3]       \
                 + h1.x*f2b[4] + h1.y*f2b[5] + h1.z*f2b[6] + h1.w*f2b[7];      \
        float w2 = h0.x*f2c[0] + h0.y*f2c[1] + h0.z*f2c[2] + h0.w*f2c[3]       \
                 + h1.x*f2c[4] + h1.y*f2c[5] + h1.z*f2c[6] + h1.w*f2c[7];      \
        float w3 = h0.x*f2d[0] + h0.y*f2d[1] + h0.z*f2d[2] + h0.w*f2d[3]       \
                 + h1.x*f2d[4] + h1.y*f2d[5] + h1.z*f2d[6] + h1.w*f2d[7];      \
        float dot = (XG).y*ea.y + (XG).z*ea.z + (XG).w*ea.w;                   \
        float av = w1 * (XG).x;                                                \
        float bv = w2 * ea.x;                                                  \
        a0 += w0 * (XG).x * ea.x;                                              \
        a1 += av * ea.y;  a2 += av * ea.z;  a3 += av * ea.w;                   \
        a4 += w3 * dot * INV3;                                                 \
        a5 += bv * (XG).y;  a6 += bv * (XG).z;  a7 += bv * (XG).w;             \
    }

    for (int base = 0; base < deg; base += 32) {
        int cnt = deg - base; if (cnt > 32) cnt = 32;

        // cooperative prefetch: one lane per edge, all loads in flight at once
        if (lane < cnt) {
            int eid = sBe[w][base + lane];
            pf[w][lane]      = __ldg((const float4*)eattr + eid);
            pf[w][32 + lane] = __ldg((const float4*)g_h + (size_t)eid*2);
            pf[w][64 + lane] = __ldg((const float4*)g_h + (size_t)eid*2 + 1);
        }
        __syncwarp();

        int i = 0;
        for (; i + 4 <= cnt; i += 4) {      // ILP-4 scattered gather
            int n0 = sBn[w][base + i    ], n1 = sBn[w][base + i + 1];
            int n2 = sBn[w][base + i + 2], n3 = sBn[w][base + i + 3];
            float4 x0 = __ldg((const float4*)g_s1v + n0*32 + lane);
            float4 x1 = __ldg((const float4*)g_s1v + n1*32 + lane);
            float4 x2 = __ldg((const float4*)g_s1v + n2*32 + lane);
            float4 x3 = __ldg((const float4*)g_s1v + n3*32 + lane);
            COMPUTE(i    , x0);
            COMPUTE(i + 1, x1);
            COMPUTE(i + 2, x2);
            COMPUTE(i + 3, x3);
        }
        for (; i < cnt; i++) {
            int nb = sBn[w][base + i];
            float4 x = __ldg((const float4*)g_s1v + nb*32 + lane);
            COMPUTE(i, x);
        }
        __syncwarp();   // protect pf before next chunk overwrites
    }
    #undef COMPUTE

    // Fused epilogue: reuse pf as accumulator stage
    float4* st = pf[w];
    st[lane*2]     = make_float4(a0, a1, a2, a3);
    st[lane*2 + 1] = make_float4(a4, a5, a6, a7);
    __syncwarp();

    float os = 0.f, ox = 0.f, oy = 0.f, oz = 0.f;
    #pragma unroll
    for (int u = 0; u < 32; u++) {
        float4 B0 = st[u*2];        // LDS broadcast
        float4 B1 = st[u*2 + 1];
        float ws0 = sWs[u*32 + lane], ws1 = sWs[(u + 32)*32 + lane];
        float wv0 = sWv[u*32 + lane], wv1 = sWv[(u + 32)*32 + lane];
        os += B0.x*ws0 + B1.x*ws1;
        ox += B0.y*wv0 + B1.y*wv1;
        oy += B0.z*wv0 + B1.z*wv1;
        oz += B0.w*wv0 + B1.w*wv1;
    }

    const float* sc = g_sc + (size_t)n * 128;
    float* o = out + (size_t)n * 128;
    o[lane]            = os*LIN2 + sc[lane];
    o[32 + lane*3 + 0] = ox*LIN2 + sc[32 + lane*3 + 0];
    o[32 + lane*3 + 1] = oy*LIN2 + sc[32 + lane*3 + 1];
    o[32 + lane*3 + 2] = oz*LIN2 + sc[32 + lane*3 + 2];
}

// ---------------------------------------------------------------------------
extern "C" void kernel_launch(void* const* d_in, const int* in_sizes, int n_in,
                              void* d_out, int out_size)
{
    const float* ee    = (const float*)d_in[0];
    const float* nattr = (const float*)d_in[1];
    const float* nf    = (const float*)d_in[2];
    const int*   eidx  = (const int*)d_in[3];    // int32 or int64 — sniffed in-kernel
    const float* eattr = (const float*)d_in[4];
    const float* W1s   = (const float*)d_in[5];
    const float* W1v   = (const float*)d_in[6];
    const float* Wfc1  = (const float*)d_in[7];
    const float* Wfc2  = (const float*)d_in[8];
    const float* W2s   = (const float*)d_in[9];
    const float* W2v   = (const float*)d_in[10];
    const float* WscS  = (const float*)d_in[11];
    const float* WscV  = (const float*)d_in[12];

    k_zero  <<<196,  256>>>();
    k_place <<<3125, 256>>>(eidx, ee, Wfc1);
    k_pre   <<<3125, 256>>>(nf, nattr, W1s, W1v, WscS, WscV);
    k_gather<<<6250, 256>>>(eattr, Wfc2, W2s, W2v, (float*)d_out);
}